// round 5
// baseline (speedup 1.0000x reference)
#include <cuda_runtime.h>

#ifndef BATCH_THREADS
#define BATCH_THREADS 256
#endif

// ---------- packed f32x2 helpers ----------
typedef unsigned long long u64;

__device__ __forceinline__ u64 pk(float lo, float hi) {
    u64 r;
    asm("mov.b64 %0, {%1, %2};" : "=l"(r) : "f"(lo), "f"(hi));
    return r;
}
__device__ __forceinline__ void upk(float& lo, float& hi, u64 v) {
    asm("mov.b64 {%0, %1}, %2;" : "=f"(lo), "=f"(hi) : "l"(v));
}
__device__ __forceinline__ u64 f2fma(u64 a, u64 b, u64 c) {
    u64 d;
    asm("fma.rn.f32x2 %0, %1, %2, %3;" : "=l"(d) : "l"(a), "l"(b), "l"(c));
    return d;
}
__device__ __forceinline__ u64 f2mul(u64 a, u64 b) {
    u64 d;
    asm("mul.rn.f32x2 %0, %1, %2;" : "=l"(d) : "l"(a), "l"(b));
    return d;
}
__device__ __forceinline__ u64 f2add(u64 a, u64 b) {
    u64 d;
    asm("add.rn.f32x2 %0, %1, %2;" : "=l"(d) : "l"(a), "l"(b));
    return d;
}

// packed 3x3 matmul: o = a*b (flat row-major [9]), 27 FFMA2
__device__ __forceinline__ void mm3p(u64* __restrict__ o,
                                     const u64* __restrict__ a,
                                     const u64* __restrict__ b) {
#pragma unroll
    for (int i = 0; i < 3; i++) {
#pragma unroll
        for (int j = 0; j < 3; j++) {
            u64 s = f2mul(a[3 * i + 0], b[0 + j]);
            s = f2fma(a[3 * i + 1], b[3 + j], s);
            s = f2fma(a[3 * i + 2], b[6 + j], s);
            o[3 * i + j] = s;
        }
    }
}

// packed 3x3 matmul-accumulate: o = a*b + add, 27 FFMA2 (no extra adds)
__device__ __forceinline__ void mm3p_acc(u64* __restrict__ o,
                                         const u64* __restrict__ a,
                                         const u64* __restrict__ b,
                                         const u64* __restrict__ add) {
#pragma unroll
    for (int i = 0; i < 3; i++) {
#pragma unroll
        for (int j = 0; j < 3; j++) {
            u64 s = f2fma(a[3 * i + 0], b[0 + j], add[3 * i + j]);
            s = f2fma(a[3 * i + 1], b[3 + j], s);
            s = f2fma(a[3 * i + 2], b[6 + j], s);
            o[3 * i + j] = s;
        }
    }
}

__global__ void __launch_bounds__(BATCH_THREADS, 5)
transop_expm_kernel(const float* __restrict__ c,
                    const float* __restrict__ x,
                    const float* __restrict__ psi,
                    float* __restrict__ out,
                    int B) {
    // psi pre-scaled by 1/8 (folds the 2^-3 scaling-and-squaring scale for free)
    __shared__ u64 sp2[54];
    if (threadIdx.x < 54) {
        float v = psi[threadIdx.x] * 0.125f;
        sp2[threadIdx.x] = pk(v, v);
    }
    __syncthreads();

    int t = blockIdx.x * BATCH_THREADS + threadIdx.x;  // items 2t, 2t+1
    if (2 * t >= B) return;

    // ---- c for both items: 12 contiguous floats = 3x float4 ----
    const float4* c4 = reinterpret_cast<const float4*>(c);
    float4 A  = c4[3 * t + 0];
    float4 Bv = c4[3 * t + 1];
    float4 Cv = c4[3 * t + 2];
    u64 cc[6];
    cc[0] = pk(A.x,  Bv.z);
    cc[1] = pk(A.y,  Bv.w);
    cc[2] = pk(A.z,  Cv.x);
    cc[3] = pk(A.w,  Cv.y);
    cc[4] = pk(Bv.x, Cv.z);
    cc[5] = pk(Bv.y, Cv.w);

    // ---- T = sum_m cc[m] * (psi[m]/8)  (packed, both items) ----
    u64 T[9];
#pragma unroll
    for (int p = 0; p < 9; p++) {
        u64 s = f2mul(cc[0], sp2[p]);
#pragma unroll
        for (int m = 1; m < 6; m++) s = f2fma(cc[m], sp2[m * 9 + p], s);
        T[p] = s;
    }

    // ---- degree-7 Taylor, Horner in T^2 (uniform control flow):
    //   E = A0 + T2*(A1 + T2*(A2 + T2*A3)),  Ak = a_k*I + b_k*T
    //   a = (1, 1/2, 1/24, 1/720), b = (1, 1/6, 1/120, 1/5040)
    u64 T2[9];
    mm3p(T2, T, T);

    const u64 kb3 = pk(1.0f / 5040.0f, 1.0f / 5040.0f);
    const u64 ka3 = pk(1.0f / 720.0f,  1.0f / 720.0f);
    const u64 kb2 = pk(1.0f / 120.0f,  1.0f / 120.0f);
    const u64 ka2 = pk(1.0f / 24.0f,   1.0f / 24.0f);
    const u64 kb1 = pk(1.0f / 6.0f,    1.0f / 6.0f);
    const u64 ka1 = pk(0.5f, 0.5f);
    const u64 k1  = pk(1.0f, 1.0f);
    const u64 kz  = 0ull;

    u64 Acc[9], L[9];
    // Acc = A3
#pragma unroll
    for (int p = 0; p < 9; p++)
        Acc[p] = f2fma(T[p], kb3, (p == 0 || p == 4 || p == 8) ? ka3 : kz);

    // L = A2 ; Acc = T2*Acc + L
#pragma unroll
    for (int p = 0; p < 9; p++)
        L[p] = f2fma(T[p], kb2, (p == 0 || p == 4 || p == 8) ? ka2 : kz);
    {
        u64 Tmp[9];
        mm3p_acc(Tmp, T2, Acc, L);
#pragma unroll
        for (int p = 0; p < 9; p++) Acc[p] = Tmp[p];
    }

    // L = A1 ; Acc = T2*Acc + L
#pragma unroll
    for (int p = 0; p < 9; p++)
        L[p] = f2fma(T[p], kb1, (p == 0 || p == 4 || p == 8) ? ka1 : kz);
    {
        u64 Tmp[9];
        mm3p_acc(Tmp, T2, Acc, L);
#pragma unroll
        for (int p = 0; p < 9; p++) Acc[p] = Tmp[p];
    }

    // L = A0 = I + T ; Acc = T2*Acc + L
#pragma unroll
    for (int p = 0; p < 9; p++) L[p] = T[p];
    L[0] = f2add(L[0], k1);
    L[4] = f2add(L[4], k1);
    L[8] = f2add(L[8], k1);
    {
        u64 Tmp[9];
        mm3p_acc(Tmp, T2, Acc, L);
#pragma unroll
        for (int p = 0; p < 9; p++) Acc[p] = Tmp[p];
    }

    // ---- exactly 3 squarings (uniform, unrolled) ----
#pragma unroll
    for (int i = 0; i < 3; i++) {
        u64 Q[9];
        mm3p(Q, Acc, Acc);
#pragma unroll
        for (int p = 0; p < 9; p++) Acc[p] = Q[p];
    }

    // ---- x loads (deferred) ----
    const float2* x2 = reinterpret_cast<const float2*>(x);
    float2 X0 = x2[3 * t + 0];
    float2 X1 = x2[3 * t + 1];
    float2 X2 = x2[3 * t + 2];
    u64 xv0 = pk(X0.x, X1.y);
    u64 xv1 = pk(X0.y, X2.x);
    u64 xv2 = pk(X1.x, X2.y);

    u64 y0 = f2fma(Acc[0], xv0, f2fma(Acc[1], xv1, f2mul(Acc[2], xv2)));
    u64 y1 = f2fma(Acc[3], xv0, f2fma(Acc[4], xv1, f2mul(Acc[5], xv2)));
    u64 y2 = f2fma(Acc[6], xv0, f2fma(Acc[7], xv1, f2mul(Acc[8], xv2)));

    float y00, y10, y01, y11, y02, y12;
    upk(y00, y10, y0);
    upk(y01, y11, y1);
    upk(y02, y12, y2);

    float2* o2 = reinterpret_cast<float2*>(out);
    o2[3 * t + 0] = make_float2(y00, y01);
    o2[3 * t + 1] = make_float2(y02, y10);
    o2[3 * t + 2] = make_float2(y11, y12);
}

extern "C" void kernel_launch(void* const* d_in, const int* in_sizes, int n_in,
                              void* d_out, int out_size) {
    // Identify inputs by element count: psi=54, c=B*6, x=B*3
    const float* c = nullptr;
    const float* x = nullptr;
    const float* psi = nullptr;
    long long maxsz = 0;
    for (int i = 0; i < n_in; i++)
        if ((long long)in_sizes[i] > maxsz) maxsz = in_sizes[i];
    int B = (int)(maxsz / 6);
    for (int i = 0; i < n_in; i++) {
        if (in_sizes[i] == 54) psi = (const float*)d_in[i];
        else if (in_sizes[i] == B * 6) c = (const float*)d_in[i];
        else if (in_sizes[i] == B * 3) x = (const float*)d_in[i];
    }

    float* out = (float*)d_out;
    int nthreads = (B + 1) / 2;  // 2 items per thread
    int grid = (nthreads + BATCH_THREADS - 1) / BATCH_THREADS;
    transop_expm_kernel<<<grid, BATCH_THREADS>>>(c, x, psi, out, B);
}

// round 6
// speedup vs baseline: 1.5406x; 1.5406x over previous
#include <cuda_runtime.h>

#ifndef BATCH_THREADS
#define BATCH_THREADS 256
#endif

__global__ void __launch_bounds__(BATCH_THREADS, 6)
transop_expm_kernel(const float* __restrict__ c,
                    const float* __restrict__ x,
                    const float* __restrict__ psi,
                    float* __restrict__ out,
                    int B) {
    __shared__ float sp[54];
    if (threadIdx.x < 54) sp[threadIdx.x] = psi[threadIdx.x];
    __syncthreads();

    int b = blockIdx.x * BATCH_THREADS + threadIdx.x;
    if (b >= B) return;

    // ---- c[b,0..5] : three float2 loads (aligned: 6*b even) ----
    const float2* c2 = reinterpret_cast<const float2*>(c);
    float2 ca = c2[3 * b + 0];
    float2 cb = c2[3 * b + 1];
    float2 cd = c2[3 * b + 2];
    float cc[6] = {ca.x, ca.y, cb.x, cb.y, cd.x, cd.y};

    // ---- T = sum_m cc[m] * psi[m]  (9 entries, 54 FMA) ----
    float T[9];
#pragma unroll
    for (int p = 0; p < 9; p++) {
        float s = cc[0] * sp[p];
#pragma unroll
        for (int m = 1; m < 6; m++) s = fmaf(cc[m], sp[m * 9 + p], s);
        T[p] = s;
    }

    // ---- split: T = mu*I + T0, T0 traceless ----
    float mu = (T[0] + T[4] + T[8]) * (1.0f / 3.0f);
    T[0] -= mu;
    T[4] -= mu;
    T[8] -= mu;

    // ---- char poly of T0:  T0^3 = p*T0 + q*I ----
    // p = tr(T0^2)/2 = (d0^2+d1^2+d2^2)/2 + (T01*T10 + T02*T20 + T12*T21)
    float u = T[0] * T[0];
    u = fmaf(T[4], T[4], u);
    u = fmaf(T[8], T[8], u);
    float v = T[1] * T[3];
    v = fmaf(T[2], T[6], v);
    v = fmaf(T[5], T[7], v);
    float pc = fmaf(0.5f, u, v);
    // q = det(T0) = r0 . (r1 x r2)
    float m0 = fmaf(T[4], T[8], -T[5] * T[7]);
    float m1 = fmaf(T[5], T[6], -T[3] * T[8]);
    float m2 = fmaf(T[3], T[7], -T[4] * T[6]);
    float qc = T[0] * m0;
    qc = fmaf(T[1], m1, qc);
    qc = fmaf(T[2], m2, qc);

    // ---- scale to Y = T0/8: pY = p/64, qY = q/512 ----
    float pY = pc * (1.0f / 64.0f);
    float qY = qc * (1.0f / 512.0f);

    // ---- exp(Y) mod (X^3 - pY X - qY), Horner deg-11:
    //   S <- S*X + w_k  with  (s0,s1,s2)*X = (s2*qY, s0 + s2*pY, s1)
    float s0 = 1.0f / 39916800.0f;  // 1/11!
    float s1 = 0.0f, s2 = 0.0f;
    const float w[11] = {1.0f,
                         1.0f,
                         1.0f / 2.0f,
                         1.0f / 6.0f,
                         1.0f / 24.0f,
                         1.0f / 120.0f,
                         1.0f / 720.0f,
                         1.0f / 5040.0f,
                         1.0f / 40320.0f,
                         1.0f / 362880.0f,
                         1.0f / 3628800.0f};  // 1/k!, k=0..10
#pragma unroll
    for (int k = 10; k >= 0; k--) {
        float n0 = fmaf(s2, qY, w[k]);
        float n1 = fmaf(s2, pY, s0);
        s2 = s1;
        s0 = n0;
        s1 = n1;
    }

    // ---- 3 squarings in coefficient space (exp(2Y), exp(4Y), exp(8Y)) ----
#pragma unroll
    for (int i = 0; i < 3; i++) {
        float d0 = s0 + s0;
        float b0 = s0 * s0;
        float b1 = d0 * s1;
        float b2 = fmaf(s1, s1, d0 * s2);
        float b3 = (s1 + s1) * s2;
        float b4 = s2 * s2;
        // reduce: X^3 = pY X + qY ; X^4 = pY X^2 + qY X
        s0 = fmaf(qY, b3, b0);
        s1 = fmaf(pY, b3, fmaf(qY, b4, b1));
        s2 = fmaf(pY, b4, b2);
    }
    // now exp(T0) = s0*I + s1*Y + s2*Y^2,  Y = T0/8

    // ---- fold e^mu and the 1/8, 1/64 basis scales into coefficients ----
    float emu = __expf(mu);
    float g0 = s0 * emu;
    float g1 = s1 * emu * 0.125f;
    float g2 = s2 * emu * 0.015625f;

    // ---- y = g0*x + g1*(T0 x) + g2*(T0 (T0 x)) ----
    float x0 = x[3 * b + 0];
    float x1 = x[3 * b + 1];
    float x2 = x[3 * b + 2];

    float v0 = fmaf(T[0], x0, fmaf(T[1], x1, T[2] * x2));
    float v1 = fmaf(T[3], x0, fmaf(T[4], x1, T[5] * x2));
    float v2 = fmaf(T[6], x0, fmaf(T[7], x1, T[8] * x2));

    float w0 = fmaf(T[0], v0, fmaf(T[1], v1, T[2] * v2));
    float w1 = fmaf(T[3], v0, fmaf(T[4], v1, T[5] * v2));
    float w2 = fmaf(T[6], v0, fmaf(T[7], v1, T[8] * v2));

    float y0 = fmaf(g0, x0, fmaf(g1, v0, g2 * w0));
    float y1 = fmaf(g0, x1, fmaf(g1, v1, g2 * w1));
    float y2 = fmaf(g0, x2, fmaf(g1, v2, g2 * w2));

    out[3 * b + 0] = y0;
    out[3 * b + 1] = y1;
    out[3 * b + 2] = y2;
}

extern "C" void kernel_launch(void* const* d_in, const int* in_sizes, int n_in,
                              void* d_out, int out_size) {
    // Identify inputs by element count: psi=54, c=B*6, x=B*3
    const float* c = nullptr;
    const float* x = nullptr;
    const float* psi = nullptr;
    long long maxsz = 0;
    for (int i = 0; i < n_in; i++)
        if ((long long)in_sizes[i] > maxsz) maxsz = in_sizes[i];
    int B = (int)(maxsz / 6);
    for (int i = 0; i < n_in; i++) {
        if (in_sizes[i] == 54) psi = (const float*)d_in[i];
        else if (in_sizes[i] == B * 6) c = (const float*)d_in[i];
        else if (in_sizes[i] == B * 3) x = (const float*)d_in[i];
    }

    float* out = (float*)d_out;
    int grid = (B + BATCH_THREADS - 1) / BATCH_THREADS;
    transop_expm_kernel<<<grid, BATCH_THREADS>>>(c, x, psi, out, B);
}